// round 5
// baseline (speedup 1.0000x reference)
#include <cuda_runtime.h>
#include <cooperative_groups.h>
#include <math.h>

namespace cg = cooperative_groups;

#define TT 196            // tokens
#define TQ 49             // token float4-quads per channel
#define CC 640            // channels
#define CLN 16            // cluster: 8 channel-chunks x 2 tensors
#define CHUNK 80          // channels per CTA
#define NSP 5             // channel splits in column passes (5*16 = 80)
#define CSP 16            // channels per split
#define TPB 256
#define NW 8
#define TILE_ELEMS (CHUNK * TT)        // 15680
#define TILE_BYTES (TILE_ELEMS * 4)    // 62720

__device__ __forceinline__ float warp_sum(float v) {
#pragma unroll
    for (int o = 16; o; o >>= 1) v += __shfl_xor_sync(0xffffffffu, v, o);
    return v;
}
__device__ __forceinline__ float warp_max(float v) {
#pragma unroll
    for (int o = 16; o; o >>= 1) v = fmaxf(v, __shfl_xor_sync(0xffffffffu, v, o));
    return v;
}

__device__ __forceinline__ unsigned su32(const void* p) {
    unsigned a;
    asm("{ .reg .u64 t; cvta.to.shared.u64 t, %1; cvt.u32.u64 %0, t; }"
        : "=r"(a) : "l"(p));
    return a;
}
__device__ __forceinline__ void mbar_init(unsigned mb, unsigned cnt) {
    asm volatile("mbarrier.init.shared.b64 [%0], %1;" :: "r"(mb), "r"(cnt) : "memory");
}
__device__ __forceinline__ void mbar_expect_tx(unsigned mb, unsigned bytes) {
    asm volatile("mbarrier.arrive.expect_tx.shared.b64 _, [%0], %1;"
                 :: "r"(mb), "r"(bytes) : "memory");
}
__device__ __forceinline__ void mbar_wait(unsigned mb, unsigned parity) {
    asm volatile(
        "{\n\t.reg .pred p;\n\t"
        "WL_%=:\n\t"
        "mbarrier.try_wait.parity.shared.b64 p, [%0], %1;\n\t"
        "@!p bra WL_%=;\n\t}"
        :: "r"(mb), "r"(parity) : "memory");
}
__device__ __forceinline__ void bulk_g2s(unsigned dst, const void* src,
                                         unsigned bytes, unsigned mb) {
    asm volatile(
        "cp.async.bulk.shared::cta.global.mbarrier::complete_tx::bytes "
        "[%0], [%1], %2, [%3];"
        :: "r"(dst), "l"(src), "r"(bytes), "r"(mb) : "memory");
}

struct State {
    // pbuf[0] doubles as the remote-readable partial (p0 / mpart / lp) for
    // each column pass; safe because phases are fenced by cluster syncs.
    alignas(16) float pbuf[NSP][TT];
    alignas(16) float a4[TT];     // 1 + attn (float4-readable)
    alignas(16) float invn[TT];   // 1/||token||
    alignas(16) float kw[TT];     // k * invn
    float m[TT];                  // m, then logits
    float bar[CHUNK];             // my bar chunk   (remote-read by peer)
    float v[CHUNK];               // my v chunk     (remote-read by peer)
    float obar[CHUNK];            // local copy of peer bar / peer v
    float h[32];                  // MLP hidden
    float red[2];                 // softmax reduce
    alignas(8) unsigned long long mbar;
};

// Column pass: pbuf[sp][t] = sum over this split's channels of w[c]*x (or x*x).
// 245 active threads, LDS.128 along token dim.
template <bool SQ>
__device__ __forceinline__ void col_pass(const float4* __restrict__ t4,
                                         const float* __restrict__ w,
                                         State& s, int tid) {
    const int q  = tid % TQ;
    const int sp = tid / TQ;     // 0..5 (sp==5 idle for tid>=245)
    if (sp < NSP) {
        float4 acc = make_float4(0.f, 0.f, 0.f, 0.f);
        const int c0 = sp * CSP;
#pragma unroll
        for (int i = 0; i < CSP; ++i) {
            float4 x = t4[(c0 + i) * TQ + q];
            if (SQ) {
                acc.x = fmaf(x.x, x.x, acc.x);
                acc.y = fmaf(x.y, x.y, acc.y);
                acc.z = fmaf(x.z, x.z, acc.z);
                acc.w = fmaf(x.w, x.w, acc.w);
            } else {
                float ww = w[c0 + i];
                acc.x = fmaf(ww, x.x, acc.x);
                acc.y = fmaf(ww, x.y, acc.y);
                acc.z = fmaf(ww, x.z, acc.z);
                acc.w = fmaf(ww, x.w, acc.w);
            }
        }
        reinterpret_cast<float4*>(s.pbuf)[sp * TQ + q] = acc;
    }
    __syncthreads();
    // fold splits into pbuf[0] (per-tid read-then-write, no race)
    if (tid < TT) {
        float r = s.pbuf[0][tid] + s.pbuf[1][tid] + s.pbuf[2][tid]
                + s.pbuf[3][tid] + s.pbuf[4][tid];
        s.pbuf[0][tid] = r;
    }
}

// Row pass: out[c] = scale * sum_t w[t]*tile[c][t], float4 along tokens.
__device__ __forceinline__ void row_pass(const float4* __restrict__ t4,
                                         const float4* __restrict__ w4,
                                         float* __restrict__ out, float scale,
                                         int wid, int lane) {
    for (int c = wid; c < CHUNK; c += NW) {
        const float4* row = t4 + c * TQ;
        float4 x = row[lane];
        float4 w = w4[lane];
        float acc = x.x * w.x;
        acc = fmaf(x.y, w.y, acc);
        acc = fmaf(x.z, w.z, acc);
        acc = fmaf(x.w, w.w, acc);
        if (lane < TQ - 32) {   // lanes 0..16 cover quads 32..48
            float4 x2 = row[32 + lane];
            float4 w2 = w4[32 + lane];
            acc = fmaf(x2.x, w2.x, acc);
            acc = fmaf(x2.y, w2.y, acc);
            acc = fmaf(x2.z, w2.z, acc);
            acc = fmaf(x2.w, w2.w, acc);
        }
        acc = warp_sum(acc);
        if (lane == 0) out[c] = acc * scale;
    }
}

__global__ void __launch_bounds__(TPB, 3)
cross_attn_cluster16(const float* __restrict__ cls_all, const float* __restrict__ qry_all,
                     const float* __restrict__ cw1, const float* __restrict__ cb1,
                     const float* __restrict__ cw2, const float* __restrict__ cb2,
                     const float* __restrict__ qw1, const float* __restrict__ qb1,
                     const float* __restrict__ qw2, const float* __restrict__ qb2,
                     float* __restrict__ oc_all, float* __restrict__ oq_all) {
    extern __shared__ float tile[];   // [CHUNK][TT]
    __shared__ State s;

    cg::cluster_group cl = cg::this_cluster();
    const int tid  = threadIdx.x;
    const int lane = tid & 31;
    const int wid  = tid >> 5;
    const unsigned rank  = cl.block_rank();           // 0..15
    const bool isClass   = rank < 8;
    const unsigned chunk = rank & 7;
    const unsigned gbase = isClass ? 0u : 8u;
    const unsigned peer  = rank ^ 8u;
    const int batch = blockIdx.x / CLN;

    const size_t off = (size_t)batch * CC * TT + (size_t)chunk * CHUNK * TT;
    const float* X = (isClass ? cls_all : qry_all) + off;
    float*       O = (isClass ? oc_all  : oq_all ) + off;

    // Class CTAs compute m_q -> run the QUERY-side MLP, and vice versa.
    const float* w1 = isClass ? qw1 : cw1;
    const float* b1 = isClass ? qb1 : cb1;
    const float* w2 = isClass ? qw2 : cw2;
    const float* b2 = isClass ? qb2 : cb2;

    const float4* t4 = reinterpret_cast<const float4*>(tile);

    // ---- TMA bulk load of my tile ------------------------------------------
    const unsigned tileA = su32(tile);
    const unsigned mb    = su32(&s.mbar);
    if (tid == 0) mbar_init(mb, 1);
    __syncthreads();
    if (tid == 0) {
        mbar_expect_tx(mb, TILE_BYTES);
        bulk_g2s(tileA, X, TILE_BYTES, mb);
    }
    mbar_wait(mb, 0);

    // ---- Phase 1: sumsq partial over my channels ---------------------------
    col_pass<true>(t4, nullptr, s, tid);
    cl.sync();  // S1

    // ---- invn (group reduce over 8 ranks) + bar (local row reduce) ---------
    if (tid < TT) {
        float ss = 0.f;
#pragma unroll
        for (unsigned i = 0; i < 8; ++i)
            ss += cl.map_shared_rank(&s.pbuf[0][0], gbase + i)[tid];
        s.invn[tid] = 1.f / fmaxf(sqrtf(ss), 1e-12f);
    }
    __syncthreads();
    row_pass(t4, reinterpret_cast<const float4*>(s.invn), s.bar,
             1.f / (float)TT, wid, lane);
    cl.sync();  // S2

    // ---- m partial: sum_c peer_bar[c] * tile[c][t] -------------------------
    {
        const float* pbar = cl.map_shared_rank(s.bar, peer);
        if (tid < CHUNK) s.obar[tid] = pbar[tid];
    }
    __syncthreads();
    col_pass<false>(t4, s.obar, s, tid);
    cl.sync();  // S3

    // ---- m reduce, tiny MLP -> kw = k * invn, then v (local row reduce) ----
    if (tid < TT) {
        float mm = 0.f;
#pragma unroll
        for (unsigned i = 0; i < 8; ++i)
            mm += cl.map_shared_rank(&s.pbuf[0][0], gbase + i)[tid];
        s.m[tid] = mm * s.invn[tid];
    }
    __syncthreads();
    // hidden: 256 thr = 32 hidden units x 8 split-K
    {
        const int hh = tid >> 3;
        const int tg = tid & 7;
        float acc = 0.f;
        for (int t = tg; t < TT; t += 8)
            acc = fmaf(s.m[t], w1[t * 32 + hh], acc);
#pragma unroll
        for (int o = 4; o; o >>= 1) acc += __shfl_xor_sync(0xffffffffu, acc, o);
        if (tg == 0) s.h[hh] = fmaxf(acc + b1[hh], 0.f);
    }
    __syncthreads();
    if (tid < TT) {
        float acc = b2[tid];
#pragma unroll
        for (int hh = 0; hh < 32; ++hh)
            acc = fmaf(s.h[hh], w2[hh * TT + tid], acc);
        s.kw[tid] = acc * s.invn[tid];
    }
    __syncthreads();
    row_pass(t4, reinterpret_cast<const float4*>(s.kw), s.v, 1.f, wid, lane);
    cl.sync();  // S4

    // ---- logit partial: sum_c peer_v[c] * tile[c][t] -----------------------
    {
        const float* pv = cl.map_shared_rank(s.v, peer);
        if (tid < CHUNK) s.obar[tid] = pv[tid];
    }
    __syncthreads();
    col_pass<false>(t4, s.obar, s, tid);
    cl.sync();  // S5

    // ---- logits reduce, softmax --------------------------------------------
    if (tid < TT) {
        float ll = 0.f;
#pragma unroll
        for (unsigned i = 0; i < 8; ++i)
            ll += cl.map_shared_rank(&s.pbuf[0][0], gbase + i)[tid];
        s.m[tid] = ll * s.invn[tid] * 40.f;   // /0.025
    }
    __syncthreads();
    if (wid == 0) {
        float v = -3.4e38f;
        for (int t = lane; t < TT; t += 32) v = fmaxf(v, s.m[t]);
        v = warp_max(v);
        if (lane == 0) s.red[0] = v;
    }
    __syncthreads();
    if (tid < TT) s.m[tid] = __expf(s.m[tid] - s.red[0]);
    __syncthreads();
    if (wid == 0) {
        float v = 0.f;
        for (int t = lane; t < TT; t += 32) v += s.m[t];
        v = warp_sum(v);
        if (lane == 0) s.red[1] = 1.f / v;
    }
    __syncthreads();
    if (tid < TT) s.a4[tid] = 1.f + s.m[tid] * s.red[1];
    __syncthreads();

    // ---- output: out = tile * (1 + attn[token]) ----------------------------
    {
        const float4* a4 = reinterpret_cast<const float4*>(s.a4);
        float4* o4 = reinterpret_cast<float4*>(O);
        const int N4 = TILE_ELEMS / 4;   // 3920; channel row = 49 float4
        for (int i = tid; i < N4; i += TPB) {
            float4 v = t4[i];
            float4 a = a4[i % TQ];
            v.x *= a.x; v.y *= a.y; v.z *= a.z; v.w *= a.w;
            o4[i] = v;
        }
    }

    cl.sync();  // keep SMEM alive until all cluster peers finished remote reads
}

extern "C" void kernel_launch(void* const* d_in, const int* in_sizes, int n_in,
                              void* d_out, int out_size) {
    const float* cls = (const float*)d_in[0];
    const float* qry = (const float*)d_in[1];
    const float* cw1 = (const float*)d_in[2];
    const float* cb1 = (const float*)d_in[3];
    const float* cw2 = (const float*)d_in[4];
    const float* cb2 = (const float*)d_in[5];
    const float* qw1 = (const float*)d_in[6];
    const float* qb1 = (const float*)d_in[7];
    const float* qw2 = (const float*)d_in[8];
    const float* qb2 = (const float*)d_in[9];

    const int B = in_sizes[0] / (CC * TT);  // 512
    float* oc = (float*)d_out;
    float* oq = oc + (size_t)B * CC * TT;

    cudaFuncSetAttribute(cross_attn_cluster16,
                         cudaFuncAttributeMaxDynamicSharedMemorySize, TILE_BYTES);
    cudaFuncSetAttribute(cross_attn_cluster16,
                         cudaFuncAttributeNonPortableClusterSizeAllowed, 1);

    cudaLaunchConfig_t cfg = {};
    cfg.gridDim  = dim3(B * CLN, 1, 1);
    cfg.blockDim = dim3(TPB, 1, 1);
    cfg.dynamicSmemBytes = TILE_BYTES;
    cudaLaunchAttribute attrs[1];
    attrs[0].id = cudaLaunchAttributeClusterDimension;
    attrs[0].val.clusterDim = {CLN, 1, 1};
    cfg.attrs = attrs;
    cfg.numAttrs = 1;

    cudaLaunchKernelEx(&cfg, cross_attn_cluster16,
                       cls, qry, cw1, cb1, cw2, cb2, qw1, qb1, qw2, qb2, oc, oq);
}

// round 7
// speedup vs baseline: 1.5965x; 1.5965x over previous
#include <cuda_runtime.h>
#include <cooperative_groups.h>
#include <math.h>

namespace cg = cooperative_groups;

#define TT 196            // tokens
#define CC 640            // channels
#define CLN 10            // cluster: 5 channel-chunks x 2 tensors
#define GRP 5             // chunks per tensor
#define CHUNK 128         // channels per CTA
#define TPB 256
#define NW 8
#define TILE_ELEMS (CHUNK * TT)        // 25088
#define TILE_BYTES (TILE_ELEMS * 4)    // 100352

__device__ __forceinline__ float warp_sum(float v) {
#pragma unroll
    for (int o = 16; o; o >>= 1) v += __shfl_xor_sync(0xffffffffu, v, o);
    return v;
}
__device__ __forceinline__ float warp_max(float v) {
#pragma unroll
    for (int o = 16; o; o >>= 1) v = fmaxf(v, __shfl_xor_sync(0xffffffffu, v, o));
    return v;
}

__device__ __forceinline__ unsigned su32(const void* p) {
    unsigned a;
    asm("{ .reg .u64 t; cvta.to.shared.u64 t, %1; cvt.u32.u64 %0, t; }"
        : "=r"(a) : "l"(p));
    return a;
}
__device__ __forceinline__ void mbar_init(unsigned mb, unsigned cnt) {
    asm volatile("mbarrier.init.shared.b64 [%0], %1;" :: "r"(mb), "r"(cnt) : "memory");
}
__device__ __forceinline__ void mbar_expect_tx(unsigned mb, unsigned bytes) {
    asm volatile("mbarrier.arrive.expect_tx.shared.b64 _, [%0], %1;"
                 :: "r"(mb), "r"(bytes) : "memory");
}
__device__ __forceinline__ void mbar_wait(unsigned mb, unsigned parity) {
    asm volatile(
        "{\n\t.reg .pred p;\n\t"
        "WL_%=:\n\t"
        "mbarrier.try_wait.parity.shared.b64 p, [%0], %1;\n\t"
        "@!p bra WL_%=;\n\t}"
        :: "r"(mb), "r"(parity) : "memory");
}
__device__ __forceinline__ void bulk_g2s(unsigned dst, const void* src,
                                         unsigned bytes, unsigned mb) {
    asm volatile(
        "cp.async.bulk.shared::cta.global.mbarrier::complete_tx::bytes "
        "[%0], [%1], %2, [%3];"
        :: "r"(dst), "l"(src), "r"(bytes), "r"(mb) : "memory");
}

struct State {
    // part is reused for sumsq / m / logit partials; phases fenced by cl.sync.
    alignas(16) float part[TT];   // remote-read by group
    alignas(16) float a4[TT];     // 1 + attn (float4-readable)
    float invn[TT];               // 1/||token||
    float m[TT];                  // m, then logits
    float kw[TT];                 // k * invn
    float bar[CHUNK];             // my bar chunk   (remote-read by peer)
    float v[CHUNK];               // my v chunk     (remote-read by peer)
    float obar[CHUNK];            // local copy of peer bar / peer v
    float h[32];                  // MLP hidden
    float red[2];                 // softmax reduce
    alignas(8) unsigned long long mbar;
};

__global__ void __launch_bounds__(TPB, 2)
cross_attn_cluster10(const float* __restrict__ cls_all, const float* __restrict__ qry_all,
                     const float* __restrict__ cw1, const float* __restrict__ cb1,
                     const float* __restrict__ cw2, const float* __restrict__ cb2,
                     const float* __restrict__ qw1, const float* __restrict__ qb1,
                     const float* __restrict__ qw2, const float* __restrict__ qb2,
                     float* __restrict__ oc_all, float* __restrict__ oq_all) {
    extern __shared__ float tile[];   // [CHUNK][TT]
    __shared__ State s;

    cg::cluster_group cl = cg::this_cluster();
    const int tid  = threadIdx.x;
    const int lane = tid & 31;
    const int wid  = tid >> 5;
    const unsigned rank  = cl.block_rank();           // 0..9
    const bool isClass   = rank < GRP;
    const unsigned chunk = isClass ? rank : rank - GRP;
    const unsigned gbase = isClass ? 0u : (unsigned)GRP;
    const unsigned peer  = isClass ? rank + GRP : rank - GRP;
    const int batch = blockIdx.x / CLN;

    const size_t off = (size_t)batch * CC * TT + (size_t)chunk * CHUNK * TT;
    const float* X = (isClass ? cls_all : qry_all) + off;
    float*       O = (isClass ? oc_all  : oq_all ) + off;

    // Class CTAs compute m_q (= qbar . ct[u]) -> run the QUERY-side MLP, and
    // symmetrically for query CTAs. (Mapping verified rel_err ~6e-9 in R2-R5.)
    const float* w1 = isClass ? qw1 : cw1;
    const float* b1 = isClass ? qb1 : cb1;
    const float* w2 = isClass ? qw2 : cw2;
    const float* b2 = isClass ? qb2 : cb2;

    // ---- TMA bulk load of my tile ------------------------------------------
    const unsigned tileA = su32(tile);
    const unsigned mb    = su32(&s.mbar);
    if (tid == 0) mbar_init(mb, 1);
    __syncthreads();
    if (tid == 0) {
        mbar_expect_tx(mb, TILE_BYTES);
        bulk_g2s(tileA, X, TILE_BYTES, mb);
    }
    mbar_wait(mb, 0);

    // ---- Phase 1: sumsq partial over my channels ---------------------------
    if (tid < TT) {
        float acc = 0.f;
#pragma unroll 8
        for (int c = 0; c < CHUNK; ++c) {
            float v = tile[c * TT + tid];
            acc = fmaf(v, v, acc);
        }
        s.part[tid] = acc;
    }
    cl.sync();  // S1

    // ---- invn (group reduce over 5 ranks) + bar (local row reduce) ---------
    if (tid < TT) {
        float ss = 0.f;
#pragma unroll
        for (unsigned i = 0; i < GRP; ++i)
            ss += cl.map_shared_rank(s.part, gbase + i)[tid];
        s.invn[tid] = 1.f / fmaxf(sqrtf(ss), 1e-12f);
    }
    __syncthreads();
    for (int c = wid; c < CHUNK; c += NW) {
        float acc = 0.f;
        for (int t = lane; t < TT; t += 32)
            acc = fmaf(tile[c * TT + t], s.invn[t], acc);
        acc = warp_sum(acc);
        if (lane == 0) s.bar[c] = acc * (1.f / (float)TT);
    }
    cl.sync();  // S2

    // ---- m partial: sum_c peer_bar[c] * tile[c][t] -------------------------
    {
        const float* pbar = cl.map_shared_rank(s.bar, peer);
        if (tid < CHUNK) s.obar[tid] = pbar[tid];
    }
    __syncthreads();
    if (tid < TT) {
        float acc = 0.f;
#pragma unroll 8
        for (int c = 0; c < CHUNK; ++c)
            acc = fmaf(s.obar[c], tile[c * TT + tid], acc);
        s.part[tid] = acc;
    }
    cl.sync();  // S3

    // ---- m reduce, tiny MLP -> kw = k * invn, then v (local row reduce) ----
    if (tid < TT) {
        float mm = 0.f;
#pragma unroll
        for (unsigned i = 0; i < GRP; ++i)
            mm += cl.map_shared_rank(s.part, gbase + i)[tid];
        s.m[tid] = mm * s.invn[tid];
    }
    __syncthreads();
    // hidden: 256 thr = 32 hidden units x 8 split-K
    {
        const int hh = tid >> 3;
        const int tg = tid & 7;
        float acc = 0.f;
        for (int t = tg; t < TT; t += 8)
            acc = fmaf(s.m[t], w1[t * 32 + hh], acc);
#pragma unroll
        for (int o = 4; o; o >>= 1) acc += __shfl_xor_sync(0xffffffffu, acc, o);
        if (tg == 0) s.h[hh] = fmaxf(acc + b1[hh], 0.f);
    }
    __syncthreads();
    if (tid < TT) {
        float acc = b2[tid];
#pragma unroll
        for (int hh = 0; hh < 32; ++hh)
            acc = fmaf(s.h[hh], w2[hh * TT + tid], acc);
        s.kw[tid] = acc * s.invn[tid];
    }
    __syncthreads();
    for (int c = wid; c < CHUNK; c += NW) {
        float acc = 0.f;
        for (int t = lane; t < TT; t += 32)
            acc = fmaf(tile[c * TT + t], s.kw[t], acc);
        acc = warp_sum(acc);
        if (lane == 0) s.v[c] = acc;
    }
    cl.sync();  // S4

    // ---- logit partial: sum_c peer_v[c] * tile[c][t] -----------------------
    {
        const float* pv = cl.map_shared_rank(s.v, peer);
        if (tid < CHUNK) s.obar[tid] = pv[tid];
    }
    __syncthreads();
    if (tid < TT) {
        float acc = 0.f;
#pragma unroll 8
        for (int c = 0; c < CHUNK; ++c)
            acc = fmaf(s.obar[c], tile[c * TT + tid], acc);
        s.part[tid] = acc;
    }
    cl.sync();  // S5

    // ---- logits reduce, softmax --------------------------------------------
    if (tid < TT) {
        float ll = 0.f;
#pragma unroll
        for (unsigned i = 0; i < GRP; ++i)
            ll += cl.map_shared_rank(s.part, gbase + i)[tid];
        s.m[tid] = ll * s.invn[tid] * 40.f;   // /0.025
    }
    __syncthreads();
    if (wid == 0) {
        float v = -3.4e38f;
        for (int t = lane; t < TT; t += 32) v = fmaxf(v, s.m[t]);
        v = warp_max(v);
        if (lane == 0) s.red[0] = v;
    }
    __syncthreads();
    if (tid < TT) s.m[tid] = __expf(s.m[tid] - s.red[0]);
    __syncthreads();
    if (wid == 0) {
        float v = 0.f;
        for (int t = lane; t < TT; t += 32) v += s.m[t];
        v = warp_sum(v);
        if (lane == 0) s.red[1] = 1.f / v;
    }
    __syncthreads();
    if (tid < TT) s.a4[tid] = 1.f + s.m[tid] * s.red[1];
    __syncthreads();

    // ---- output: out = tile * (1 + attn[token]) ----------------------------
    {
        const float4* t4 = reinterpret_cast<const float4*>(tile);
        const float4* a4 = reinterpret_cast<const float4*>(s.a4);
        float4* o4 = reinterpret_cast<float4*>(O);
        const int N4 = TILE_ELEMS / 4;   // 6272; channel row = 49 float4
        for (int i = tid; i < N4; i += TPB) {
            float4 v = t4[i];
            float4 a = a4[i % 49];
            v.x *= a.x; v.y *= a.y; v.z *= a.z; v.w *= a.w;
            o4[i] = v;
        }
    }

    cl.sync();  // keep SMEM alive until all cluster peers finished remote reads
}

extern "C" void kernel_launch(void* const* d_in, const int* in_sizes, int n_in,
                              void* d_out, int out_size) {
    const float* cls = (const float*)d_in[0];
    const float* qry = (const float*)d_in[1];
    const float* cw1 = (const float*)d_in[2];
    const float* cb1 = (const float*)d_in[3];
    const float* cw2 = (const float*)d_in[4];
    const float* cb2 = (const float*)d_in[5];
    const float* qw1 = (const float*)d_in[6];
    const float* qb1 = (const float*)d_in[7];
    const float* qw2 = (const float*)d_in[8];
    const float* qb2 = (const float*)d_in[9];

    const int B = in_sizes[0] / (CC * TT);  // 512
    float* oc = (float*)d_out;
    float* oq = oc + (size_t)B * CC * TT;

    cudaFuncSetAttribute(cross_attn_cluster10,
                         cudaFuncAttributeMaxDynamicSharedMemorySize, TILE_BYTES);
    cudaFuncSetAttribute(cross_attn_cluster10,
                         cudaFuncAttributeNonPortableClusterSizeAllowed, 1);

    cudaLaunchConfig_t cfg = {};
    cfg.gridDim  = dim3(B * CLN, 1, 1);
    cfg.blockDim = dim3(TPB, 1, 1);
    cfg.dynamicSmemBytes = TILE_BYTES;
    cudaLaunchAttribute attrs[1];
    attrs[0].id = cudaLaunchAttributeClusterDimension;
    attrs[0].val.clusterDim = {CLN, 1, 1};
    cfg.attrs = attrs;
    cfg.numAttrs = 1;

    cudaLaunchKernelEx(&cfg, cross_attn_cluster10,
                       cls, qry, cw1, cb1, cw2, cb2, qw1, qb1, qw2, qb2, oc, oq);
}

// round 8
// speedup vs baseline: 1.6406x; 1.0276x over previous
#include <cuda_runtime.h>
#include <cooperative_groups.h>
#include <math.h>

namespace cg = cooperative_groups;

#define TT 196            // tokens
#define CC 640            // channels
#define CLN 10            // cluster: 5 channel-chunks x 2 tensors
#define GRP 5             // chunks per tensor
#define CHUNK 128         // channels per CTA
#define TPB 512
#define NW 16
#define CSPL 2            // channel splits in column passes
#define CSPC (CHUNK/CSPL) // 64 channels per split
#define TILE_ELEMS (CHUNK * TT)        // 25088
#define TILE_BYTES (TILE_ELEMS * 4)    // 100352

__device__ __forceinline__ float warp_sum(float v) {
#pragma unroll
    for (int o = 16; o; o >>= 1) v += __shfl_xor_sync(0xffffffffu, v, o);
    return v;
}
__device__ __forceinline__ float warp_max(float v) {
#pragma unroll
    for (int o = 16; o; o >>= 1) v = fmaxf(v, __shfl_xor_sync(0xffffffffu, v, o));
    return v;
}

__device__ __forceinline__ unsigned su32(const void* p) {
    unsigned a;
    asm("{ .reg .u64 t; cvta.to.shared.u64 t, %1; cvt.u32.u64 %0, t; }"
        : "=r"(a) : "l"(p));
    return a;
}
__device__ __forceinline__ void mbar_init(unsigned mb, unsigned cnt) {
    asm volatile("mbarrier.init.shared.b64 [%0], %1;" :: "r"(mb), "r"(cnt) : "memory");
}
__device__ __forceinline__ void mbar_expect_tx(unsigned mb, unsigned bytes) {
    asm volatile("mbarrier.arrive.expect_tx.shared.b64 _, [%0], %1;"
                 :: "r"(mb), "r"(bytes) : "memory");
}
__device__ __forceinline__ void mbar_wait(unsigned mb, unsigned parity) {
    asm volatile(
        "{\n\t.reg .pred p;\n\t"
        "WL_%=:\n\t"
        "mbarrier.try_wait.parity.shared.b64 p, [%0], %1;\n\t"
        "@!p bra WL_%=;\n\t}"
        :: "r"(mb), "r"(parity) : "memory");
}
__device__ __forceinline__ void bulk_g2s(unsigned dst, const void* src,
                                         unsigned bytes, unsigned mb) {
    asm volatile(
        "cp.async.bulk.shared::cta.global.mbarrier::complete_tx::bytes "
        "[%0], [%1], %2, [%3];"
        :: "r"(dst), "l"(src), "r"(bytes), "r"(mb) : "memory");
}

struct State {
    // part[0] is the remote-readable partial for each column pass; phases
    // are fenced by cluster syncs so reuse across passes is safe.
    alignas(16) float part[CSPL][TT];
    alignas(16) float a4[TT];     // 1 + attn (float4-readable)
    float invn[TT];               // 1/||token||
    float m[TT];                  // m, then logits
    float kw[TT];                 // k * invn
    float bar[CHUNK];             // my bar chunk   (remote-read by peer)
    float v[CHUNK];               // my v chunk     (remote-read by peer)
    float obar[CHUNK];            // local copy of peer bar / peer v
    float h[32];                  // MLP hidden
    float red[2];                 // softmax reduce
    alignas(8) unsigned long long mbar;
};

__global__ void __launch_bounds__(TPB, 2)
cross_attn_cluster10(const float* __restrict__ cls_all, const float* __restrict__ qry_all,
                     const float* __restrict__ cw1, const float* __restrict__ cb1,
                     const float* __restrict__ cw2, const float* __restrict__ cb2,
                     const float* __restrict__ qw1, const float* __restrict__ qb1,
                     const float* __restrict__ qw2, const float* __restrict__ qb2,
                     float* __restrict__ oc_all, float* __restrict__ oq_all) {
    extern __shared__ float tile[];   // [CHUNK][TT]
    __shared__ State s;

    cg::cluster_group cl = cg::this_cluster();
    const int tid  = threadIdx.x;
    const int lane = tid & 31;
    const int wid  = tid >> 5;
    const unsigned rank  = cl.block_rank();           // 0..9
    const bool isClass   = rank < GRP;
    const unsigned chunk = isClass ? rank : rank - GRP;
    const unsigned gbase = isClass ? 0u : (unsigned)GRP;
    const unsigned peer  = isClass ? rank + GRP : rank - GRP;
    const int batch = blockIdx.x / CLN;

    const size_t off = (size_t)batch * CC * TT + (size_t)chunk * CHUNK * TT;
    const float* X = (isClass ? cls_all : qry_all) + off;
    float*       O = (isClass ? oc_all  : oq_all ) + off;

    // Class CTAs compute m_q -> run the QUERY-side MLP, and vice versa.
    const float* w1 = isClass ? qw1 : cw1;
    const float* b1 = isClass ? qb1 : cb1;
    const float* w2 = isClass ? qw2 : cw2;
    const float* b2 = isClass ? qb2 : cb2;

    // column-pass indexing: 2 splits x 196 tokens = 392 active threads
    const int ct = tid % TT;          // token
    const int cs = tid / TT;          // split (0,1; >=2 idle)

    // ---- TMA bulk load of my tile ------------------------------------------
    const unsigned tileA = su32(tile);
    const unsigned mb    = su32(&s.mbar);
    if (tid == 0) mbar_init(mb, 1);
    __syncthreads();
    if (tid == 0) {
        mbar_expect_tx(mb, TILE_BYTES);
        bulk_g2s(tileA, X, TILE_BYTES, mb);
    }
    mbar_wait(mb, 0);

    // ---- Phase 1: sumsq partial over my channels ---------------------------
    if (cs < CSPL) {
        const float* p = tile + cs * CSPC * TT + ct;
        float acc = 0.f;
#pragma unroll 8
        for (int c = 0; c < CSPC; ++c) {
            float v = p[c * TT];
            acc = fmaf(v, v, acc);
        }
        s.part[cs][ct] = acc;
    }
    __syncthreads();
    if (tid < TT) s.part[0][tid] += s.part[1][tid];
    cl.sync();  // S1

    // ---- invn (group reduce over 5 ranks) + bar (local row reduce) ---------
    if (tid < TT) {
        float ss = 0.f;
#pragma unroll
        for (unsigned i = 0; i < GRP; ++i)
            ss += cl.map_shared_rank(&s.part[0][0], gbase + i)[tid];
        s.invn[tid] = 1.f / fmaxf(sqrtf(ss), 1e-12f);
    }
    __syncthreads();
    for (int c = wid; c < CHUNK; c += NW) {
        float acc = 0.f;
        for (int t = lane; t < TT; t += 32)
            acc = fmaf(tile[c * TT + t], s.invn[t], acc);
        acc = warp_sum(acc);
        if (lane == 0) s.bar[c] = acc * (1.f / (float)TT);
    }
    cl.sync();  // S2

    // ---- m partial: sum_c peer_bar[c] * tile[c][t] -------------------------
    {
        const float* pbar = cl.map_shared_rank(s.bar, peer);
        if (tid < CHUNK) s.obar[tid] = pbar[tid];
    }
    __syncthreads();
    if (cs < CSPL) {
        const float* p = tile + cs * CSPC * TT + ct;
        const float* wv = s.obar + cs * CSPC;
        float acc = 0.f;
#pragma unroll 8
        for (int c = 0; c < CSPC; ++c)
            acc = fmaf(wv[c], p[c * TT], acc);
        s.part[cs][ct] = acc;
    }
    __syncthreads();
    if (tid < TT) s.part[0][tid] += s.part[1][tid];
    cl.sync();  // S3

    // ---- m reduce, tiny MLP -> kw = k * invn, then v (local row reduce) ----
    if (tid < TT) {
        float mm = 0.f;
#pragma unroll
        for (unsigned i = 0; i < GRP; ++i)
            mm += cl.map_shared_rank(&s.part[0][0], gbase + i)[tid];
        s.m[tid] = mm * s.invn[tid];
    }
    __syncthreads();
    // hidden: 512 thr = 32 hidden units x 16 split-K (16-lane subgroups)
    {
        const int hh = tid >> 4;     // 0..31
        const int tg = tid & 15;     // 0..15
        float acc = 0.f;
        for (int t = tg; t < TT; t += 16)
            acc = fmaf(s.m[t], w1[t * 32 + hh], acc);
#pragma unroll
        for (int o = 8; o; o >>= 1) acc += __shfl_xor_sync(0xffffffffu, acc, o);
        if (tg == 0) s.h[hh] = fmaxf(acc + b1[hh], 0.f);
    }
    __syncthreads();
    if (tid < TT) {
        float acc = b2[tid];
#pragma unroll
        for (int hh = 0; hh < 32; ++hh)
            acc = fmaf(s.h[hh], w2[hh * TT + tid], acc);
        s.kw[tid] = acc * s.invn[tid];
    }
    __syncthreads();
    for (int c = wid; c < CHUNK; c += NW) {
        float acc = 0.f;
        for (int t = lane; t < TT; t += 32)
            acc = fmaf(tile[c * TT + t], s.kw[t], acc);
        acc = warp_sum(acc);
        if (lane == 0) s.v[c] = acc;
    }
    cl.sync();  // S4

    // ---- logit partial: sum_c peer_v[c] * tile[c][t] -----------------------
    {
        const float* pv = cl.map_shared_rank(s.v, peer);
        if (tid < CHUNK) s.obar[tid] = pv[tid];
    }
    __syncthreads();
    if (cs < CSPL) {
        const float* p = tile + cs * CSPC * TT + ct;
        const float* wv = s.obar + cs * CSPC;
        float acc = 0.f;
#pragma unroll 8
        for (int c = 0; c < CSPC; ++c)
            acc = fmaf(wv[c], p[c * TT], acc);
        s.part[cs][ct] = acc;
    }
    __syncthreads();
    if (tid < TT) s.part[0][tid] += s.part[1][tid];
    cl.sync();  // S5

    // ---- logits reduce, softmax --------------------------------------------
    if (tid < TT) {
        float ll = 0.f;
#pragma unroll
        for (unsigned i = 0; i < GRP; ++i)
            ll += cl.map_shared_rank(&s.part[0][0], gbase + i)[tid];
        s.m[tid] = ll * s.invn[tid] * 40.f;   // /0.025
    }
    __syncthreads();
    if (wid == 0) {
        float v = -3.4e38f;
        for (int t = lane; t < TT; t += 32) v = fmaxf(v, s.m[t]);
        v = warp_max(v);
        if (lane == 0) s.red[0] = v;
    }
    __syncthreads();
    if (tid < TT) s.m[tid] = __expf(s.m[tid] - s.red[0]);
    __syncthreads();
    if (wid == 0) {
        float v = 0.f;
        for (int t = lane; t < TT; t += 32) v += s.m[t];
        v = warp_sum(v);
        if (lane == 0) s.red[1] = 1.f / v;
    }
    __syncthreads();
    if (tid < TT) s.a4[tid] = 1.f + s.m[tid] * s.red[1];
    __syncthreads();

    // ---- output: out = tile * (1 + attn[token]) ----------------------------
    {
        const float4* t4 = reinterpret_cast<const float4*>(tile);
        const float4* a4 = reinterpret_cast<const float4*>(s.a4);
        float4* o4 = reinterpret_cast<float4*>(O);
        const int N4 = TILE_ELEMS / 4;   // 6272; channel row = 49 float4
        for (int i = tid; i < N4; i += TPB) {
            float4 v = t4[i];
            float4 a = a4[i % 49];
            v.x *= a.x; v.y *= a.y; v.z *= a.z; v.w *= a.w;
            o4[i] = v;
        }
    }

    cl.sync();  // keep SMEM alive until all cluster peers finished remote reads
}

extern "C" void kernel_launch(void* const* d_in, const int* in_sizes, int n_in,
                              void* d_out, int out_size) {
    const float* cls = (const float*)d_in[0];
    const float* qry = (const float*)d_in[1];
    const float* cw1 = (const float*)d_in[2];
    const float* cb1 = (const float*)d_in[3];
    const float* cw2 = (const float*)d_in[4];
    const float* cb2 = (const float*)d_in[5];
    const float* qw1 = (const float*)d_in[6];
    const float* qb1 = (const float*)d_in[7];
    const float* qw2 = (const float*)d_in[8];
    const float* qb2 = (const float*)d_in[9];

    const int B = in_sizes[0] / (CC * TT);  // 512
    float* oc = (float*)d_out;
    float* oq = oc + (size_t)B * CC * TT;

    cudaFuncSetAttribute(cross_attn_cluster10,
                         cudaFuncAttributeMaxDynamicSharedMemorySize, TILE_BYTES);
    cudaFuncSetAttribute(cross_attn_cluster10,
                         cudaFuncAttributeNonPortableClusterSizeAllowed, 1);

    cudaLaunchConfig_t cfg = {};
    cfg.gridDim  = dim3(B * CLN, 1, 1);
    cfg.blockDim = dim3(TPB, 1, 1);
    cfg.dynamicSmemBytes = TILE_BYTES;
    cudaLaunchAttribute attrs[1];
    attrs[0].id = cudaLaunchAttributeClusterDimension;
    attrs[0].val.clusterDim = {CLN, 1, 1};
    cfg.attrs = attrs;
    cfg.numAttrs = 1;

    cudaLaunchKernelEx(&cfg, cross_attn_cluster10,
                       cls, qry, cw1, cb1, cw2, cb2, qw1, qb1, qw2, qb2, oc, oq);
}